// round 15
// baseline (speedup 1.0000x reference)
#include <cuda_runtime.h>
#include <cuda_fp16.h>
#include <math.h>

#define BB 4
#define NN 128
#define FF 128
#define SS 5
#define TGLOB 32
#define LL 2
#define TBL 256
#define LMAX 16.0f
#define TBL_SCALE (TBL / LMAX)
#define TBLK (TBL / 8)          /* table blocks per layer = 32 */
#define NBLOCKS 256

// ---------------- persistent scratch (device globals; no allocation) ------
__device__ float g_posbuf[2][BB * NN * 3];
__device__ uint2 g_veczbuf[2][BB * NN * FF];      // half2(v0,v1), half2(v2,z)
__device__ __half2 g_tblh[LL * TBL * 256];        // (w_t,w_{t+1}) pairs, ell 0..1
__device__ unsigned g_count = 0;
__device__ volatile unsigned g_sense = 0;

__device__ __forceinline__ unsigned pack2(float a, float b) {
    __half2 h = __floats2half2_rn(a, b);
    return *reinterpret_cast<unsigned*>(&h);
}
__device__ __forceinline__ float2 unpack2(unsigned u) {
    __half2 h = *reinterpret_cast<__half2*>(&u);
    return __half22float2(h);
}

// sense-reversal grid barrier; safe: all NBLOCKS co-resident by launch_bounds
__device__ __forceinline__ void grid_barrier(int tid) {
    __syncthreads();
    if (tid == 0) {
        __threadfence();
        unsigned my = g_sense;
        if (atomicAdd(&g_count, 1u) == NBLOCKS - 1) {
            g_count = 0;
            __threadfence();
            g_sense = my + 1;
        } else {
            while (g_sense == my) { }
        }
    }
    __syncthreads();
}

// ---------------- single persistent kernel: prep + both layers ------------
__global__ __launch_bounds__(512, 2) void k_all(const float* __restrict__ pos_in,
                                                const int* __restrict__ node_features,
                                                const float* __restrict__ gf,
                                                const float* __restrict__ W_embed,
                                                const float* __restrict__ b_embed,
                                                const float* __restrict__ Wr1,
                                                const float* __restrict__ br1,
                                                const float* __restrict__ Wr2,
                                                const float* __restrict__ Wnode,
                                                const float* __restrict__ c1w,
                                                const float* __restrict__ c2w,
                                                const float* __restrict__ c3w,
                                                const float* __restrict__ Wmix0,
                                                const float* __restrict__ Wmix1,
                                                const float* __restrict__ Wg1,
                                                const float* __restrict__ Wg2,
                                                const float* __restrict__ Wvout,
                                                float* __restrict__ out) {
    const int bid = blockIdx.x;
    const int tid = threadIdx.x;

    __shared__ float sp[NN * 3];
    __shared__ float sp0[NN * 3];
    __shared__ float4 sData[2][NN];
    __shared__ float2 sD2[2][NN];
    __shared__ float rp[8 * 1024];   // multi-purpose scratch
    __shared__ float sA[2 * 512];
    __shared__ float sred[2 * 512];
    __shared__ float shp[2][2][16];
    __shared__ float sh[2][16];
    __shared__ float rb[2][3][4];
    __shared__ float zred[2][FF];

    // =================== phase 0: prep =====================================
    if (bid < TBLK * LL) {
        // ---- table block: 8 pair-rows (9 samples), m split 4-way ----
        const int i = bid / TBLK;
        const int tb0 = (bid % TBLK) * 8;
        const int c = tid & 127;
        const int qm = tid >> 7;                 // 0..3
        float* h = rp;                           // [9][64]
        float* redt = rp + 1024;                 // [3][9][2][128]
        if (tid < 64) {
            float w1 = Wr1[i * 64 + tid];
            float b1 = br1[i * 64 + tid];
#pragma unroll
            for (int j = 0; j < 9; j++) {
                float lng = (float)(tb0 + j) * (LMAX / (float)TBL);
                float p = lng * w1 + b1;
                h[j * 64 + tid] = p / (1.0f + expf(-p));
            }
        }
        __syncthreads();
        const float* W = Wr2 + i * 64 * 512 + c;
        float acc[9][2];
#pragma unroll
        for (int j = 0; j < 9; j++) { acc[j][0] = 0.f; acc[j][1] = 0.f; }
#pragma unroll 4
        for (int mm = 0; mm < 16; mm++) {
            int m = qm * 16 + mm;
            float w0 = W[m * 512 + 0];
            float w1v = W[m * 512 + 128];
#pragma unroll
            for (int j = 0; j < 9; j++) {
                float hm = h[j * 64 + m];
                acc[j][0] = fmaf(hm, w0, acc[j][0]);
                acc[j][1] = fmaf(hm, w1v, acc[j][1]);
            }
        }
        if (qm > 0) {
#pragma unroll
            for (int j = 0; j < 9; j++) {
                redt[((qm - 1) * 9 + j) * 256 + c]       = acc[j][0];
                redt[((qm - 1) * 9 + j) * 256 + 128 + c] = acc[j][1];
            }
        }
        __syncthreads();
        if (qm == 0) {
            const float sc0 = 1.0f / 16.0f;
            const float sc1 = 1.7320508075688772f / 16.0f;
            float f0[9], f1[9];
#pragma unroll
            for (int j = 0; j < 9; j++) {
                f0[j] = (acc[j][0] + redt[j * 256 + c] + redt[(9 + j) * 256 + c]
                         + redt[(18 + j) * 256 + c]) * sc0;
                f1[j] = (acc[j][1] + redt[j * 256 + 128 + c] + redt[(9 + j) * 256 + 128 + c]
                         + redt[(18 + j) * 256 + 128 + c]) * sc1;
            }
#pragma unroll
            for (int j = 0; j < 8; j++) {
                __half2* dst = g_tblh + ((size_t)i * TBL + tb0 + j) * 256 + c * 2;
                dst[0] = __float22half2_rn(make_float2(f0[j], f0[j + 1]));
                dst[1] = __float22half2_rn(make_float2(f1[j], f1[j + 1]));
            }
        }
    } else if (bid < TBLK * LL + BB * NN / 4) {
        // ---- init block: 4 nodes ----
        const int bn0 = (bid - TBLK * LL) * 4;
        const int n = tid >> 7;                  // 0..3
        const int c = tid & 127;
        const int bn = bn0 + n;
        const int b = bn / NN;
        float* srow = rp;                        // [4][128]
        float* partz = rp + 512;                 // [4][4][128]

        int nf = node_features[bn];
        float s = W_embed[(nf - 1) * FF + c] + b_embed[c];
#pragma unroll 8
        for (int t = 0; t < TGLOB; t++)
            s = fmaf(gf[b * TGLOB + t], W_embed[(SS + t) * FF + c], s);
        srow[n * FF + c] = s;
        if (c < 3) g_posbuf[0][bn * 3 + c] = pos_in[bn * 3 + c];
        __syncthreads();

        const int lane = tid & 31;
        const int grp = tid >> 5;                // 0..15
        const int nz = grp >> 2;
        const int q4 = grp & 3;
        const int c4 = lane * 4;
        const float* W = Wnode + c4;
        float4 z = make_float4(0.f, 0.f, 0.f, 0.f);
#pragma unroll
        for (int kk = 0; kk < 32; kk++) {
            int k = q4 * 32 + kk;
            float4 w4 = *(const float4*)(W + k * FF);
            float sv = srow[nz * FF + k];
            z.x = fmaf(sv, w4.x, z.x); z.y = fmaf(sv, w4.y, z.y);
            z.z = fmaf(sv, w4.z, z.z); z.w = fmaf(sv, w4.w, z.w);
        }
        __syncthreads();
        *(float4*)&partz[(q4 * 4 + nz) * FF + c4] = z;
        __syncthreads();

        float zsum = partz[(0 * 4 + n) * FF + c] + partz[(1 * 4 + n) * FF + c]
                   + partz[(2 * 4 + n) * FF + c] + partz[(3 * 4 + n) * FF + c];
        g_veczbuf[0][bn * FF + c] = make_uint2(pack2(0.f, 0.f), pack2(0.f, zsum));
    }

    // =================== layers ============================================
    const int r0 = (bid & 63) * 2;
    const int b = bid >> 6;
    const int c = tid & 127;
    const int q = tid >> 7;

    for (int layer = 0; layer < LL; layer++) {
        grid_barrier(tid);
        const int p = layer & 1;

        for (int idx = tid; idx < NN * 3; idx += 512) {
            sp[idx]  = g_posbuf[p][b * NN * 3 + idx];
            sp0[idx] = pos_in[b * NN * 3 + idx];
        }
        __syncthreads();

        // ---- geometry for 2 receivers ----
        if (tid < 2 * NN) {
            const int rr = tid >> 7;
            const int s = tid & (NN - 1);
            const int r = r0 + rr;
            const float rx = sp[r * 3 + 0], ry = sp[r * 3 + 1], rz = sp[r * 3 + 2];
            float dx0 = sp0[r * 3 + 0] - sp0[s * 3 + 0];
            float dy0 = sp0[r * 3 + 1] - sp0[s * 3 + 1];
            float dz0 = sp0[r * 3 + 2] - sp0[s * 3 + 2];
            float l0 = sqrtf(dx0 * dx0 + dy0 * dy0 + dz0 * dz0 + 1e-12f);
            float env = (l0 < 10.0f) ? 0.5f * (cosf(l0 * 0.3141592653589793f) + 1.0f) : 0.0f;
            if (s == r) env = 0.0f;

            float vx = rx - sp[s * 3 + 0];
            float vy = ry - sp[s * 3 + 1];
            float vz = rz - sp[s * 3 + 2];
            float lng = sqrtf(vx * vx + vy * vy + vz * vz + 1e-12f);
            float inv = 1.0f / lng;
            float ux = vx * inv, uy = vy * inv, uz = vz * inv;

            float tp = fminf(lng * TBL_SCALE, (float)TBL - 1.001f);
            int it = (int)tp;
            float fr = tp - (float)it;
            float a0 = env * (1.0f - fr);
            float a1 = env * fr;

            sData[rr][s] = make_float4(ux, uy, uz, a0);
            sD2[rr][s]   = make_float2(a1, __int_as_float(it));
        }
        __syncthreads();

        // ---- per-channel accumulation ----
        float A[2][4];
#pragma unroll
        for (int rr = 0; rr < 2; rr++)
#pragma unroll
            for (int k = 0; k < 4; k++) A[rr][k] = 0.f;

        {
            const __half2* tb = g_tblh + (size_t)layer * TBL * 256;
            const uint2* vecz = g_veczbuf[p] + b * NN * FF;
#pragma unroll 4
            for (int s = q * 32; s < q * 32 + 32; s++) {
                uint2 vzp = vecz[s * FF + c];
                float2 v01 = unpack2(vzp.x);
                float2 v2z = unpack2(vzp.y);
#pragma unroll
                for (int rr = 0; rr < 2; rr++) {
                    float4 d0 = sData[rr][s];
                    float2 d1 = sD2[rr][s];
                    float a0 = d0.w, a1 = d1.x;
                    int it = __float_as_int(d1.y);

                    uint2 w = *(const uint2*)(tb + (size_t)it * 256 + (c << 1));
                    float2 f0 = unpack2(w.x);
                    float2 f1 = unpack2(w.y);
                    float Rw0 = fmaf(a0, f0.x, a1 * f0.y);
                    float Rw1 = fmaf(a0, f1.x, a1 * f1.y);

                    float f = v2z.y;
                    f = fmaf(v01.x, d0.x, f);
                    f = fmaf(v01.y, d0.y, f);
                    f = fmaf(v2z.x, d0.z, f);

                    float t1 = Rw1 * f;
                    A[rr][0] = fmaf(Rw0, f, A[rr][0]);
                    A[rr][1] = fmaf(t1, d0.x, A[rr][1]);
                    A[rr][2] = fmaf(t1, d0.y, A[rr][2]);
                    A[rr][3] = fmaf(t1, d0.z, A[rr][3]);
                }
            }
        }

        if (q > 0) {
#pragma unroll
            for (int rr = 0; rr < 2; rr++)
#pragma unroll
                for (int k = 0; k < 4; k++)
                    rp[(q - 1) * 1024 + rr * 512 + k * FF + c] = A[rr][k];
        }
        __syncthreads();

        if (q == 0) {
#pragma unroll
            for (int rr = 0; rr < 2; rr++) {
                const int ro = rr * 512;
                float A0 = A[rr][0] + rp[ro + c] + rp[1024 + ro + c] + rp[2048 + ro + c];
                float A1 = A[rr][1] + rp[ro + FF + c] + rp[1024 + ro + FF + c] + rp[2048 + ro + FF + c];
                float A2 = A[rr][2] + rp[ro + 2 * FF + c] + rp[1024 + ro + 2 * FF + c] + rp[2048 + ro + 2 * FF + c];
                float A3 = A[rr][3] + rp[ro + 3 * FF + c] + rp[1024 + ro + 3 * FF + c] + rp[2048 + ro + 3 * FF + c];

                float n0 = A0 * A0;
                float n1 = A1 * A1 + A2 * A2 + A3 * A3;

                const int co = (layer * 4) * FF + c;
                float g0 = 1.f + c1w[co]      * n0 + c2w[co]      * n0 * n0 + c3w[co]      * n0 * n0 * n0;
                float g1 = 1.f + c1w[co + FF] * n1 + c2w[co + FF] * n1 * n1 + c3w[co + FF] * n1 * n1 * n1;

                sA[ro + c]          = A0 * g0;
                sA[ro + FF + c]     = A1 * g1;
                sA[ro + 2 * FF + c] = A2 * g1;
                sA[ro + 3 * FF + c] = A3 * g1;
            }
        }
        __syncthreads();

        // ---- node phase ----
        const int n = tid >> 8;
        const int t2 = tid & 255;
        const int lane = t2 & 31;
        const int q8 = t2 >> 5;
        const int c4 = lane * 4;
        const float* an = sA + n * 512;
        const int bn = b * NN + r0 + n;

        {
            const float* M0 = Wmix0 + layer * FF * FF + c4;
            const float* M1 = Wmix1 + layer * FF * FF + c4;
            float4 a0v = make_float4(0.f, 0.f, 0.f, 0.f);
            float4 a1v = a0v, a2v = a0v, a3v = a0v;
#pragma unroll
            for (int kk = 0; kk < 16; kk++) {
                int k = q8 * 16 + kk;
                float4 m0 = *(const float4*)(M0 + k * FF);
                float4 m1 = *(const float4*)(M1 + k * FF);
                float aS = an[k], b0 = an[FF + k], b1 = an[2 * FF + k], b2 = an[3 * FF + k];
                a0v.x = fmaf(aS, m0.x, a0v.x); a0v.y = fmaf(aS, m0.y, a0v.y);
                a0v.z = fmaf(aS, m0.z, a0v.z); a0v.w = fmaf(aS, m0.w, a0v.w);
                a1v.x = fmaf(b0, m1.x, a1v.x); a1v.y = fmaf(b0, m1.y, a1v.y);
                a1v.z = fmaf(b0, m1.z, a1v.z); a1v.w = fmaf(b0, m1.w, a1v.w);
                a2v.x = fmaf(b1, m1.x, a2v.x); a2v.y = fmaf(b1, m1.y, a2v.y);
                a2v.z = fmaf(b1, m1.z, a2v.z); a2v.w = fmaf(b1, m1.w, a2v.w);
                a3v.x = fmaf(b2, m1.x, a3v.x); a3v.y = fmaf(b2, m1.y, a3v.y);
                a3v.z = fmaf(b2, m1.z, a3v.z); a3v.w = fmaf(b2, m1.w, a3v.w);
            }
            float* pq = rp + q8 * 1024 + n * 512;
            *(float4*)&pq[0 * FF + c4] = a0v;
            *(float4*)&pq[1 * FF + c4] = a1v;
            *(float4*)&pq[2 * FF + c4] = a2v;
            *(float4*)&pq[3 * FF + c4] = a3v;
        }
        __syncthreads();

        for (int idx = t2; idx < 512; idx += 256) {
            float s = 0.f;
#pragma unroll
            for (int qq = 0; qq < 8; qq++) s += rp[qq * 1024 + n * 512 + idx];
            sred[n * 512 + idx] = s;
        }
        __syncthreads();

        if (t2 < 32) {
            int cc = t2 & 15, hf = t2 >> 4;
            const float* G1 = Wg1 + layer * FF * 16 + cc;
            const float* sn = sred + n * 512;
            float a = 0.f;
#pragma unroll 8
            for (int kk = 0; kk < 64; kk++) {
                int k = hf * 64 + kk;
                a = fmaf(sn[k], G1[k * 16], a);
            }
            shp[n][hf][cc] = a;
        }
        __syncthreads();
        if (t2 < 16) {
            float a = shp[n][0][t2] + shp[n][1][t2];
            sh[n][t2] = a / (1.0f + expf(-a));
        }
        __syncthreads();

        if (t2 < 128) {
            const float* G2 = Wg2 + layer * 16 * FF;
            float gate = 0.f;
#pragma unroll
            for (int j = 0; j < 16; j++) gate = fmaf(sh[n][j], G2[j * FF + t2], gate);
            float w = gate * Wvout[layer * FF + t2];
            const float* sn = sred + n * 512;
            float m0 = sn[FF + t2] * w;
            float m1 = sn[2 * FF + t2] * w;
            float m2 = sn[3 * FF + t2] * w;
#pragma unroll
            for (int off = 16; off > 0; off >>= 1) {
                m0 += __shfl_down_sync(0xffffffffu, m0, off);
                m1 += __shfl_down_sync(0xffffffffu, m1, off);
                m2 += __shfl_down_sync(0xffffffffu, m2, off);
            }
            if ((t2 & 31) == 0) {
                int wp = t2 >> 5;
                rb[n][0][wp] = m0; rb[n][1][wp] = m1; rb[n][2][wp] = m2;
            }
        }
        __syncthreads();
        if (t2 < 3) {
            float pnew = sp[(r0 + n) * 3 + t2]
                       + rb[n][t2][0] + rb[n][t2][1] + rb[n][t2][2] + rb[n][t2][3];
            g_posbuf[1 - p][bn * 3 + t2] = pnew;
            if (layer == LL - 1)
                out[bn * 3 + t2] = pnew - pos_in[bn * 3 + t2];
        }

        if (layer + 1 < LL) {
            const float* W = Wnode + (layer + 1) * FF * FF + c4;
            const float* sn = sred + n * 512;
            float4 zacc = make_float4(0.f, 0.f, 0.f, 0.f);
#pragma unroll
            for (int kk = 0; kk < 16; kk++) {
                int k = q8 * 16 + kk;
                float4 w4 = *(const float4*)(W + k * FF);
                float s = sn[k];
                zacc.x = fmaf(s, w4.x, zacc.x); zacc.y = fmaf(s, w4.y, zacc.y);
                zacc.z = fmaf(s, w4.z, zacc.z); zacc.w = fmaf(s, w4.w, zacc.w);
            }
            __syncthreads();
            *(float4*)&rp[q8 * 1024 + n * 512 + c4] = zacc;
            __syncthreads();
            if (t2 < 128) {
                float s = 0.f;
#pragma unroll
                for (int qq = 0; qq < 8; qq++) s += rp[qq * 1024 + n * 512 + t2];
                zred[n][t2] = s;
            }
            __syncthreads();
        }

        if (t2 < 128) {
            const float* sn = sred + n * 512;
            float zn = (layer + 1 < LL) ? zred[n][t2] : 0.f;
            g_veczbuf[1 - p][bn * FF + t2] =
                make_uint2(pack2(sn[FF + t2], sn[2 * FF + t2]), pack2(sn[3 * FF + t2], zn));
        }
    }
}

// ---------------------------------------------------------------------------
extern "C" void kernel_launch(void* const* d_in, const int* in_sizes, int n_in,
                              void* d_out, int out_size) {
    const float* positions     = (const float*)d_in[0];
    const int*   node_features = (const int*)d_in[1];
    const float* gf            = (const float*)d_in[2];
    const float* W_embed       = (const float*)d_in[3];
    const float* b_embed       = (const float*)d_in[4];
    const float* Wr1           = (const float*)d_in[5];
    const float* br1           = (const float*)d_in[6];
    const float* Wr2           = (const float*)d_in[7];
    const float* Wnode         = (const float*)d_in[8];
    const float* c1w           = (const float*)d_in[9];
    const float* c2w           = (const float*)d_in[10];
    const float* c3w           = (const float*)d_in[11];
    const float* Wmix0         = (const float*)d_in[12];
    const float* Wmix1         = (const float*)d_in[13];
    const float* Wg1           = (const float*)d_in[14];
    const float* Wg2           = (const float*)d_in[15];
    const float* Wvout         = (const float*)d_in[16];
    float* out = (float*)d_out;

    k_all<<<NBLOCKS, 512>>>(positions, node_features, gf, W_embed, b_embed,
                            Wr1, br1, Wr2, Wnode, c1w, c2w, c3w,
                            Wmix0, Wmix1, Wg1, Wg2, Wvout, out);
}

// round 16
// speedup vs baseline: 1.0007x; 1.0007x over previous
#include <cuda_runtime.h>
#include <cuda_fp16.h>
#include <math.h>

#define BB 4
#define NN 128
#define FF 128
#define SS 5
#define TGLOB 32
#define LL 2
#define TBL 256
#define LMAX 16.0f
#define TBL_SCALE (TBL / LMAX)
#define NBLOCKS 256
#define BPB 64                  /* blocks per batch */

// ---------------- persistent scratch (device globals; no allocation) ------
__device__ float g_posbuf[2][BB * NN * 3];
__device__ uint2 g_veczbuf[2][BB * NN * FF];      // half2(v0,v1), half2(v2,z)
__device__ __half2 g_tblh[LL * TBL * 256];        // (w_t,w_{t+1}) pairs, ell 0..1
__device__ unsigned g_count = 0;
__device__ volatile unsigned g_sense = 0;
__device__ unsigned g_countB[BB];
__device__ volatile unsigned g_senseB[BB];

__device__ __forceinline__ unsigned pack2(float a, float b) {
    __half2 h = __floats2half2_rn(a, b);
    return *reinterpret_cast<unsigned*>(&h);
}
__device__ __forceinline__ float2 unpack2(unsigned u) {
    __half2 h = *reinterpret_cast<__half2*>(&u);
    return __half22float2(h);
}

// global sense-reversal barrier; safe: all NBLOCKS co-resident (2/SM * 148)
__device__ __forceinline__ void grid_barrier(int tid) {
    __syncthreads();
    if (tid == 0) {
        __threadfence();
        unsigned my = g_sense;
        if (atomicAdd(&g_count, 1u) == NBLOCKS - 1) {
            g_count = 0;
            __threadfence();
            g_sense = my + 1;
        } else {
            while (g_sense == my) { }
        }
    }
    __syncthreads();
}

// per-batch barrier over BPB blocks
__device__ __forceinline__ void batch_barrier(int tid, int b) {
    __syncthreads();
    if (tid == 0) {
        __threadfence();
        unsigned my = g_senseB[b];
        if (atomicAdd(&g_countB[b], 1u) == BPB - 1) {
            g_countB[b] = 0;
            __threadfence();
            g_senseB[b] = my + 1;
        } else {
            while (g_senseB[b] == my) { }
        }
    }
    __syncthreads();
}

// ---------------- single persistent kernel: prep + both layers ------------
__global__ __launch_bounds__(512, 2) void k_all(const float* __restrict__ pos_in,
                                                const int* __restrict__ node_features,
                                                const float* __restrict__ gf,
                                                const float* __restrict__ W_embed,
                                                const float* __restrict__ b_embed,
                                                const float* __restrict__ Wr1,
                                                const float* __restrict__ br1,
                                                const float* __restrict__ Wr2,
                                                const float* __restrict__ Wnode,
                                                const float* __restrict__ c1w,
                                                const float* __restrict__ c2w,
                                                const float* __restrict__ c3w,
                                                const float* __restrict__ Wmix0,
                                                const float* __restrict__ Wmix1,
                                                const float* __restrict__ Wg1,
                                                const float* __restrict__ Wg2,
                                                const float* __restrict__ Wvout,
                                                float* __restrict__ out) {
    const int bid = blockIdx.x;
    const int tid = threadIdx.x;

    __shared__ float sp[NN * 3];
    __shared__ float sp0[NN * 3];
    __shared__ float4 sData[2][NN];
    __shared__ float2 sD2[2][NN];
    __shared__ float rp[8 * 1024];   // multi-purpose scratch
    __shared__ float sA[2 * 512];
    __shared__ float sred[2 * 512];
    __shared__ float shp[2][2][16];
    __shared__ float sh[2][16];
    __shared__ float rb[2][3][4];
    __shared__ float zred[2][FF];

    // =================== phase 0: prep (all 256 blocks busy) ===============
    if (bid < 128) {
        // ---- table block: 4 pair-rows (5 samples), m split 4-way ----
        const int i = bid >> 6;                  // layer 0..1
        const int tb0 = (bid & 63) * 4;          // first of 4 pair rows
        const int c = tid & 127;
        const int qm = tid >> 7;                 // 0..3
        float* h = rp;                           // [5][64]
        float* redt = rp + 512;                  // [3][5][2][128]
        if (tid < 64) {
            float w1 = Wr1[i * 64 + tid];
            float b1 = br1[i * 64 + tid];
#pragma unroll
            for (int j = 0; j < 5; j++) {
                float lng = (float)(tb0 + j) * (LMAX / (float)TBL);
                float p = lng * w1 + b1;
                h[j * 64 + tid] = p / (1.0f + expf(-p));
            }
        }
        __syncthreads();
        const float* W = Wr2 + i * 64 * 512 + c;
        float acc[5][2];
#pragma unroll
        for (int j = 0; j < 5; j++) { acc[j][0] = 0.f; acc[j][1] = 0.f; }
#pragma unroll 4
        for (int mm = 0; mm < 16; mm++) {
            int m = qm * 16 + mm;
            float w0 = W[m * 512 + 0];
            float w1v = W[m * 512 + 128];
#pragma unroll
            for (int j = 0; j < 5; j++) {
                float hm = h[j * 64 + m];
                acc[j][0] = fmaf(hm, w0, acc[j][0]);
                acc[j][1] = fmaf(hm, w1v, acc[j][1]);
            }
        }
        if (qm > 0) {
#pragma unroll
            for (int j = 0; j < 5; j++) {
                redt[((qm - 1) * 5 + j) * 256 + c]       = acc[j][0];
                redt[((qm - 1) * 5 + j) * 256 + 128 + c] = acc[j][1];
            }
        }
        __syncthreads();
        if (qm == 0) {
            const float sc0 = 1.0f / 16.0f;
            const float sc1 = 1.7320508075688772f / 16.0f;
            float f0[5], f1[5];
#pragma unroll
            for (int j = 0; j < 5; j++) {
                f0[j] = (acc[j][0] + redt[j * 256 + c] + redt[(5 + j) * 256 + c]
                         + redt[(10 + j) * 256 + c]) * sc0;
                f1[j] = (acc[j][1] + redt[j * 256 + 128 + c] + redt[(5 + j) * 256 + 128 + c]
                         + redt[(10 + j) * 256 + 128 + c]) * sc1;
            }
#pragma unroll
            for (int j = 0; j < 4; j++) {
                __half2* dst = g_tblh + ((size_t)i * TBL + tb0 + j) * 256 + c * 2;
                dst[0] = __float22half2_rn(make_float2(f0[j], f0[j + 1]));
                dst[1] = __float22half2_rn(make_float2(f1[j], f1[j + 1]));
            }
        }
    } else {
        // ---- init block: 4 nodes ----
        const int bn0 = (bid - 128) * 4;
        const int n = tid >> 7;                  // 0..3
        const int c = tid & 127;
        const int bn = bn0 + n;
        const int b = bn / NN;
        float* srow = rp;                        // [4][128]
        float* partz = rp + 512;                 // [4][4][128]

        int nf = node_features[bn];
        float s = W_embed[(nf - 1) * FF + c] + b_embed[c];
#pragma unroll 8
        for (int t = 0; t < TGLOB; t++)
            s = fmaf(gf[b * TGLOB + t], W_embed[(SS + t) * FF + c], s);
        srow[n * FF + c] = s;
        if (c < 3) g_posbuf[0][bn * 3 + c] = pos_in[bn * 3 + c];
        __syncthreads();

        const int lane = tid & 31;
        const int grp = tid >> 5;                // 0..15
        const int nz = grp >> 2;
        const int q4 = grp & 3;
        const int c4 = lane * 4;
        const float* W = Wnode + c4;
        float4 z = make_float4(0.f, 0.f, 0.f, 0.f);
#pragma unroll
        for (int kk = 0; kk < 32; kk++) {
            int k = q4 * 32 + kk;
            float4 w4 = *(const float4*)(W + k * FF);
            float sv = srow[nz * FF + k];
            z.x = fmaf(sv, w4.x, z.x); z.y = fmaf(sv, w4.y, z.y);
            z.z = fmaf(sv, w4.z, z.z); z.w = fmaf(sv, w4.w, z.w);
        }
        __syncthreads();
        *(float4*)&partz[(q4 * 4 + nz) * FF + c4] = z;
        __syncthreads();

        float zsum = partz[(0 * 4 + n) * FF + c] + partz[(1 * 4 + n) * FF + c]
                   + partz[(2 * 4 + n) * FF + c] + partz[(3 * 4 + n) * FF + c];
        g_veczbuf[0][bn * FF + c] = make_uint2(pack2(0.f, 0.f), pack2(0.f, zsum));
    }

    // =================== layers ============================================
    const int r0 = (bid & 63) * 2;
    const int b = bid >> 6;
    const int c = tid & 127;
    const int q = tid >> 7;

    for (int layer = 0; layer < LL; layer++) {
        if (layer == 0) grid_barrier(tid);       // tables/init are cross-batch
        else            batch_barrier(tid, b);   // layers are batch-local
        const int p = layer & 1;

        for (int idx = tid; idx < NN * 3; idx += 512) {
            sp[idx]  = g_posbuf[p][b * NN * 3 + idx];
            sp0[idx] = pos_in[b * NN * 3 + idx];
        }
        __syncthreads();

        // ---- geometry for 2 receivers ----
        if (tid < 2 * NN) {
            const int rr = tid >> 7;
            const int s = tid & (NN - 1);
            const int r = r0 + rr;
            const float rx = sp[r * 3 + 0], ry = sp[r * 3 + 1], rz = sp[r * 3 + 2];
            float dx0 = sp0[r * 3 + 0] - sp0[s * 3 + 0];
            float dy0 = sp0[r * 3 + 1] - sp0[s * 3 + 1];
            float dz0 = sp0[r * 3 + 2] - sp0[s * 3 + 2];
            float l0 = sqrtf(dx0 * dx0 + dy0 * dy0 + dz0 * dz0 + 1e-12f);
            float env = (l0 < 10.0f) ? 0.5f * (cosf(l0 * 0.3141592653589793f) + 1.0f) : 0.0f;
            if (s == r) env = 0.0f;

            float vx = rx - sp[s * 3 + 0];
            float vy = ry - sp[s * 3 + 1];
            float vz = rz - sp[s * 3 + 2];
            float lng = sqrtf(vx * vx + vy * vy + vz * vz + 1e-12f);
            float inv = 1.0f / lng;
            float ux = vx * inv, uy = vy * inv, uz = vz * inv;

            float tp = fminf(lng * TBL_SCALE, (float)TBL - 1.001f);
            int it = (int)tp;
            float fr = tp - (float)it;
            float a0 = env * (1.0f - fr);
            float a1 = env * fr;

            sData[rr][s] = make_float4(ux, uy, uz, a0);
            sD2[rr][s]   = make_float2(a1, __int_as_float(it));
        }
        __syncthreads();

        // ---- per-channel accumulation ----
        float A[2][4];
#pragma unroll
        for (int rr = 0; rr < 2; rr++)
#pragma unroll
            for (int k = 0; k < 4; k++) A[rr][k] = 0.f;

        {
            const __half2* tb = g_tblh + (size_t)layer * TBL * 256;
            const uint2* vecz = g_veczbuf[p] + b * NN * FF;
#pragma unroll 4
            for (int s = q * 32; s < q * 32 + 32; s++) {
                uint2 vzp = vecz[s * FF + c];
                float2 v01 = unpack2(vzp.x);
                float2 v2z = unpack2(vzp.y);
#pragma unroll
                for (int rr = 0; rr < 2; rr++) {
                    float4 d0 = sData[rr][s];
                    float2 d1 = sD2[rr][s];
                    float a0 = d0.w, a1 = d1.x;
                    int it = __float_as_int(d1.y);

                    uint2 w = *(const uint2*)(tb + (size_t)it * 256 + (c << 1));
                    float2 f0 = unpack2(w.x);
                    float2 f1 = unpack2(w.y);
                    float Rw0 = fmaf(a0, f0.x, a1 * f0.y);
                    float Rw1 = fmaf(a0, f1.x, a1 * f1.y);

                    float f = v2z.y;
                    f = fmaf(v01.x, d0.x, f);
                    f = fmaf(v01.y, d0.y, f);
                    f = fmaf(v2z.x, d0.z, f);

                    float t1 = Rw1 * f;
                    A[rr][0] = fmaf(Rw0, f, A[rr][0]);
                    A[rr][1] = fmaf(t1, d0.x, A[rr][1]);
                    A[rr][2] = fmaf(t1, d0.y, A[rr][2]);
                    A[rr][3] = fmaf(t1, d0.z, A[rr][3]);
                }
            }
        }

        if (q > 0) {
#pragma unroll
            for (int rr = 0; rr < 2; rr++)
#pragma unroll
                for (int k = 0; k < 4; k++)
                    rp[(q - 1) * 1024 + rr * 512 + k * FF + c] = A[rr][k];
        }
        __syncthreads();

        if (q == 0) {
#pragma unroll
            for (int rr = 0; rr < 2; rr++) {
                const int ro = rr * 512;
                float A0 = A[rr][0] + rp[ro + c] + rp[1024 + ro + c] + rp[2048 + ro + c];
                float A1 = A[rr][1] + rp[ro + FF + c] + rp[1024 + ro + FF + c] + rp[2048 + ro + FF + c];
                float A2 = A[rr][2] + rp[ro + 2 * FF + c] + rp[1024 + ro + 2 * FF + c] + rp[2048 + ro + 2 * FF + c];
                float A3 = A[rr][3] + rp[ro + 3 * FF + c] + rp[1024 + ro + 3 * FF + c] + rp[2048 + ro + 3 * FF + c];

                float n0 = A0 * A0;
                float n1 = A1 * A1 + A2 * A2 + A3 * A3;

                const int co = (layer * 4) * FF + c;
                float g0 = 1.f + c1w[co]      * n0 + c2w[co]      * n0 * n0 + c3w[co]      * n0 * n0 * n0;
                float g1 = 1.f + c1w[co + FF] * n1 + c2w[co + FF] * n1 * n1 + c3w[co + FF] * n1 * n1 * n1;

                sA[ro + c]          = A0 * g0;
                sA[ro + FF + c]     = A1 * g1;
                sA[ro + 2 * FF + c] = A2 * g1;
                sA[ro + 3 * FF + c] = A3 * g1;
            }
        }
        __syncthreads();

        // ---- node phase ----
        const int n = tid >> 8;
        const int t2 = tid & 255;
        const int lane = t2 & 31;
        const int q8 = t2 >> 5;
        const int c4 = lane * 4;
        const float* an = sA + n * 512;
        const int bn = b * NN + r0 + n;

        {
            const float* M0 = Wmix0 + layer * FF * FF + c4;
            const float* M1 = Wmix1 + layer * FF * FF + c4;
            float4 a0v = make_float4(0.f, 0.f, 0.f, 0.f);
            float4 a1v = a0v, a2v = a0v, a3v = a0v;
#pragma unroll
            for (int kk = 0; kk < 16; kk++) {
                int k = q8 * 16 + kk;
                float4 m0 = *(const float4*)(M0 + k * FF);
                float4 m1 = *(const float4*)(M1 + k * FF);
                float aS = an[k], b0 = an[FF + k], b1 = an[2 * FF + k], b2 = an[3 * FF + k];
                a0v.x = fmaf(aS, m0.x, a0v.x); a0v.y = fmaf(aS, m0.y, a0v.y);
                a0v.z = fmaf(aS, m0.z, a0v.z); a0v.w = fmaf(aS, m0.w, a0v.w);
                a1v.x = fmaf(b0, m1.x, a1v.x); a1v.y = fmaf(b0, m1.y, a1v.y);
                a1v.z = fmaf(b0, m1.z, a1v.z); a1v.w = fmaf(b0, m1.w, a1v.w);
                a2v.x = fmaf(b1, m1.x, a2v.x); a2v.y = fmaf(b1, m1.y, a2v.y);
                a2v.z = fmaf(b1, m1.z, a2v.z); a2v.w = fmaf(b1, m1.w, a2v.w);
                a3v.x = fmaf(b2, m1.x, a3v.x); a3v.y = fmaf(b2, m1.y, a3v.y);
                a3v.z = fmaf(b2, m1.z, a3v.z); a3v.w = fmaf(b2, m1.w, a3v.w);
            }
            float* pq = rp + q8 * 1024 + n * 512;
            *(float4*)&pq[0 * FF + c4] = a0v;
            *(float4*)&pq[1 * FF + c4] = a1v;
            *(float4*)&pq[2 * FF + c4] = a2v;
            *(float4*)&pq[3 * FF + c4] = a3v;
        }
        __syncthreads();

        for (int idx = t2; idx < 512; idx += 256) {
            float s = 0.f;
#pragma unroll
            for (int qq = 0; qq < 8; qq++) s += rp[qq * 1024 + n * 512 + idx];
            sred[n * 512 + idx] = s;
        }
        __syncthreads();

        if (t2 < 32) {
            int cc = t2 & 15, hf = t2 >> 4;
            const float* G1 = Wg1 + layer * FF * 16 + cc;
            const float* sn = sred + n * 512;
            float a = 0.f;
#pragma unroll 8
            for (int kk = 0; kk < 64; kk++) {
                int k = hf * 64 + kk;
                a = fmaf(sn[k], G1[k * 16], a);
            }
            shp[n][hf][cc] = a;
        }
        __syncthreads();
        if (t2 < 16) {
            float a = shp[n][0][t2] + shp[n][1][t2];
            sh[n][t2] = a / (1.0f + expf(-a));
        }
        __syncthreads();

        if (t2 < 128) {
            const float* G2 = Wg2 + layer * 16 * FF;
            float gate = 0.f;
#pragma unroll
            for (int j = 0; j < 16; j++) gate = fmaf(sh[n][j], G2[j * FF + t2], gate);
            float w = gate * Wvout[layer * FF + t2];
            const float* sn = sred + n * 512;
            float m0 = sn[FF + t2] * w;
            float m1 = sn[2 * FF + t2] * w;
            float m2 = sn[3 * FF + t2] * w;
#pragma unroll
            for (int off = 16; off > 0; off >>= 1) {
                m0 += __shfl_down_sync(0xffffffffu, m0, off);
                m1 += __shfl_down_sync(0xffffffffu, m1, off);
                m2 += __shfl_down_sync(0xffffffffu, m2, off);
            }
            if ((t2 & 31) == 0) {
                int wp = t2 >> 5;
                rb[n][0][wp] = m0; rb[n][1][wp] = m1; rb[n][2][wp] = m2;
            }
        }
        __syncthreads();
        if (t2 < 3) {
            float pnew = sp[(r0 + n) * 3 + t2]
                       + rb[n][t2][0] + rb[n][t2][1] + rb[n][t2][2] + rb[n][t2][3];
            g_posbuf[1 - p][bn * 3 + t2] = pnew;
            if (layer == LL - 1)
                out[bn * 3 + t2] = pnew - pos_in[bn * 3 + t2];
        }

        if (layer + 1 < LL) {
            const float* W = Wnode + (layer + 1) * FF * FF + c4;
            const float* sn = sred + n * 512;
            float4 zacc = make_float4(0.f, 0.f, 0.f, 0.f);
#pragma unroll
            for (int kk = 0; kk < 16; kk++) {
                int k = q8 * 16 + kk;
                float4 w4 = *(const float4*)(W + k * FF);
                float s = sn[k];
                zacc.x = fmaf(s, w4.x, zacc.x); zacc.y = fmaf(s, w4.y, zacc.y);
                zacc.z = fmaf(s, w4.z, zacc.z); zacc.w = fmaf(s, w4.w, zacc.w);
            }
            __syncthreads();
            *(float4*)&rp[q8 * 1024 + n * 512 + c4] = zacc;
            __syncthreads();
            if (t2 < 128) {
                float s = 0.f;
#pragma unroll
                for (int qq = 0; qq < 8; qq++) s += rp[qq * 1024 + n * 512 + t2];
                zred[n][t2] = s;
            }
            __syncthreads();
        }

        if (t2 < 128) {
            const float* sn = sred + n * 512;
            float zn = (layer + 1 < LL) ? zred[n][t2] : 0.f;
            g_veczbuf[1 - p][bn * FF + t2] =
                make_uint2(pack2(sn[FF + t2], sn[2 * FF + t2]), pack2(sn[3 * FF + t2], zn));
        }
    }
}

// ---------------------------------------------------------------------------
extern "C" void kernel_launch(void* const* d_in, const int* in_sizes, int n_in,
                              void* d_out, int out_size) {
    const float* positions     = (const float*)d_in[0];
    const int*   node_features = (const int*)d_in[1];
    const float* gf            = (const float*)d_in[2];
    const float* W_embed       = (const float*)d_in[3];
    const float* b_embed       = (const float*)d_in[4];
    const float* Wr1           = (const float*)d_in[5];
    const float* br1           = (const float*)d_in[6];
    const float* Wr2           = (const float*)d_in[7];
    const float* Wnode         = (const float*)d_in[8];
    const float* c1w           = (const float*)d_in[9];
    const float* c2w           = (const float*)d_in[10];
    const float* c3w           = (const float*)d_in[11];
    const float* Wmix0         = (const float*)d_in[12];
    const float* Wmix1         = (const float*)d_in[13];
    const float* Wg1           = (const float*)d_in[14];
    const float* Wg2           = (const float*)d_in[15];
    const float* Wvout         = (const float*)d_in[16];
    float* out = (float*)d_out;

    k_all<<<NBLOCKS, 512>>>(positions, node_features, gf, W_embed, b_embed,
                            Wr1, br1, Wr2, Wnode, c1w, c2w, c3w,
                            Wmix0, Wmix1, Wg1, Wg2, Wvout, out);
}